// round 4
// baseline (speedup 1.0000x reference)
#include <cuda_runtime.h>
#include <math.h>

#define BB 32
#define HWT 12544              // 112*112
#define CC 256
#define HID 32
#define F4_PER_ROW 64          // 256 / 4

#define GROUP 4                // batches per group (4 * 12.85MB = 51.5MB)
#define NGRP 8                 // 8 groups * 4 = 32 batches
#define KCTA 64                // CTAs per batch in pool
#define ROWS_CTA 196           // HWT / KCTA
#define ROWS_T 49              // ROWS_CTA / 4

#define BLOCKS_S 64            // scale CTAs per batch
#define F4_PER_B ((size_t)HWT * F4_PER_ROW)        // 802816
#define F4_PER_SCTA (F4_PER_B / BLOCKS_S)          // 12544

__device__ float g_psum[BB][KCTA][CC];
__device__ float g_pmax[BB][KCTA][CC];
__device__ float g_scale[BB][CC];
__device__ int   g_cnt[BB];    // zero at load; self-resetting

// ---- static stream/event setup (host objects only; no device memory) ----
static cudaStream_t s2;
static cudaEvent_t evP[NGRP], evS[NGRP];
static struct StreamInit {
    StreamInit() {
        cudaStreamCreateWithFlags(&s2, cudaStreamNonBlocking);
        for (int i = 0; i < NGRP; ++i) {
            cudaEventCreateWithFlags(&evP[i], cudaEventDisableTiming);
            cudaEventCreateWithFlags(&evS[i], cudaEventDisableTiming);
        }
    }
} s_init;

// Kernel A: pool GROUP batches + fan-in MLP tail. grid (KCTA, GROUP), 256 thr.
__global__ void __launch_bounds__(256) pool_mlp_kernel(
    const float* __restrict__ x,
    const float* __restrict__ w1, const float* __restrict__ b1,
    const float* __restrict__ w2, const float* __restrict__ b2,
    int b0)
{
    const int b   = b0 + blockIdx.y;
    const int k   = blockIdx.x;
    const int tid = threadIdx.x;
    const int c4  = tid & 63;
    const int rg  = tid >> 6;

    __shared__ float4 s_sum[4][64];
    __shared__ float4 s_mx4[4][64];
    __shared__ int    s_last;

    const size_t row0 = (size_t)b * HWT + (size_t)k * ROWS_CTA + (size_t)rg * ROWS_T;
    const float4* __restrict__ xp = reinterpret_cast<const float4*>(x) + row0 * F4_PER_ROW + c4;

    float4 s = make_float4(0.f, 0.f, 0.f, 0.f);
    float4 m = make_float4(-INFINITY, -INFINITY, -INFINITY, -INFINITY);
    #pragma unroll 7
    for (int r = 0; r < ROWS_T; ++r) {
        float4 v = __ldcg(xp + (size_t)r * F4_PER_ROW);   // cache in L2, skip L1
        s.x += v.x; s.y += v.y; s.z += v.z; s.w += v.w;
        m.x = fmaxf(m.x, v.x); m.y = fmaxf(m.y, v.y);
        m.z = fmaxf(m.z, v.z); m.w = fmaxf(m.w, v.w);
    }
    s_sum[rg][c4] = s;
    s_mx4[rg][c4] = m;
    __syncthreads();

    if (rg == 0) {
        float4 a0 = s_sum[0][c4], a1 = s_sum[1][c4], a2 = s_sum[2][c4], a3 = s_sum[3][c4];
        float4 m0 = s_mx4[0][c4], m1 = s_mx4[1][c4], m2 = s_mx4[2][c4], m3 = s_mx4[3][c4];
        float4 ss = make_float4(a0.x + a1.x + a2.x + a3.x,
                                a0.y + a1.y + a2.y + a3.y,
                                a0.z + a1.z + a2.z + a3.z,
                                a0.w + a1.w + a2.w + a3.w);
        float4 mm = make_float4(fmaxf(fmaxf(m0.x, m1.x), fmaxf(m2.x, m3.x)),
                                fmaxf(fmaxf(m0.y, m1.y), fmaxf(m2.y, m3.y)),
                                fmaxf(fmaxf(m0.z, m1.z), fmaxf(m2.z, m3.z)),
                                fmaxf(fmaxf(m0.w, m1.w), fmaxf(m2.w, m3.w)));
        reinterpret_cast<float4*>(&g_psum[b][k][0])[c4] = ss;
        reinterpret_cast<float4*>(&g_pmax[b][k][0])[c4] = mm;
    }
    __threadfence();           // release partials
    __syncthreads();

    if (tid == 0) {
        int old = atomicAdd(&g_cnt[b], 1);
        s_last = (old == KCTA - 1);
        if (s_last) {
            g_cnt[b] = 0;      // self-reset for graph replays
            __threadfence();   // acquire partials
        }
    }
    __syncthreads();
    if (!s_last) return;

    // ---- fan-in tail: reduce + dual-branch MLP + sigmoid ----
    __shared__ float s_avg[CC];
    __shared__ float s_max[CC];
    __shared__ float s_h[2 * HID];

    float sum = 0.f, mx = -INFINITY;
    #pragma unroll 8
    for (int q = 0; q < KCTA; ++q) {
        sum += __ldcg(&g_psum[b][q][tid]);
        mx = fmaxf(mx, __ldcg(&g_pmax[b][q][tid]));
    }
    s_avg[tid] = sum * (1.0f / (float)HWT);
    s_max[tid] = mx;
    __syncthreads();

    {   // hidden layer: 64 outputs (avg 0..31, max 32..63), 4 thr/output
        int oi = tid >> 2;
        int part = tid & 3;
        int j = oi & (HID - 1);
        const float* pool = (oi < HID) ? s_avg : s_max;
        float acc = 0.f;
        #pragma unroll 16
        for (int i = part * 64; i < part * 64 + 64; ++i)
            acc += pool[i] * w1[i * HID + j];
        acc += __shfl_down_sync(0xffffffffu, acc, 1);
        acc += __shfl_down_sync(0xffffffffu, acc, 2);
        if (part == 0) s_h[oi] = fmaxf(acc + b1[j], 0.f);
    }
    __syncthreads();

    {   // output layer: 2*b2 + (hA+hM) @ w2, sigmoid
        float acc = 2.0f * b2[tid];
        #pragma unroll
        for (int j = 0; j < HID; ++j)
            acc += (s_h[j] + s_h[HID + j]) * w2[j * CC + tid];
        g_scale[b][tid] = 1.0f / (1.0f + expf(-acc));
    }
}

// Kernel B: out = x * scale. grid (BLOCKS_S, GROUP), 256 thr. Reads hit L2.
__global__ void __launch_bounds__(256) scale_kernel(const float* __restrict__ x,
                                                    float* __restrict__ out,
                                                    int b0) {
    const int b   = b0 + blockIdx.y;
    const int tid = threadIdx.x;
    const float4 sc = reinterpret_cast<const float4*>(&g_scale[b][0])[tid & 63];

    const size_t base = (size_t)b * F4_PER_B + (size_t)blockIdx.x * F4_PER_SCTA;
    const float4* __restrict__ xi = reinterpret_cast<const float4*>(x) + base;
    float4* __restrict__ xo = reinterpret_cast<float4*>(out) + base;

    #pragma unroll 7
    for (int i = tid; i < F4_PER_SCTA; i += 256) {
        float4 v = __ldcs(xi + i);                 // last use: evict-first
        v.x *= sc.x; v.y *= sc.y; v.z *= sc.z; v.w *= sc.w;
        __stcs(xo + i, v);                         // streaming store
    }
}

extern "C" void kernel_launch(void* const* d_in, const int* in_sizes, int n_in,
                              void* d_out, int out_size) {
    const float* x  = (const float*)d_in[0];
    const float* w1 = (const float*)d_in[1];
    const float* b1 = (const float*)d_in[2];
    const float* w2 = (const float*)d_in[3];
    const float* b2 = (const float*)d_in[4];
    float* out = (float*)d_out;

    // Two-stream pipeline: pool(g+1) overlaps scale(g).
    // Depth guard: pool(g) waits scale(g-2) => at most 2 groups resident in L2.
    for (int g = 0; g < NGRP; ++g) {
        if (g >= 2) cudaStreamWaitEvent(0, evS[g - 2], 0);
        pool_mlp_kernel<<<dim3(KCTA, GROUP), 256>>>(x, w1, b1, w2, b2, g * GROUP);
        cudaEventRecord(evP[g], 0);
        cudaStreamWaitEvent(s2, evP[g], 0);
        scale_kernel<<<dim3(BLOCKS_S, GROUP), 256, 0, s2>>>(x, out, g * GROUP);
        cudaEventRecord(evS[g], s2);
    }
    // Join the side stream back so capture ends with a single leaf.
    cudaStreamWaitEvent(0, evS[NGRP - 1], 0);
}